// round 5
// baseline (speedup 1.0000x reference)
#include <cuda_runtime.h>
#include <cuda_bf16.h>
#include <math.h>

// Problem constants
#define NN 100000
#define DD 512
#define KK 256

// GEMM1 tile
#define BM 64
#define BK 16

// GEMM2 tile
#define KT 128
#define DT 128
#define BN2 16
#define NSPLIT 32
#define NPS (NN / NSPLIT)   // 3125

// rsum splits
#define RSPLIT 128
#define RCHUNK ((NN + RSPLIT - 1) / RSPLIT)  // 782

// ---------------- scratch (device globals; no allocations allowed) -----------
__device__ float g_data[(size_t)NN * DD];          // normalized data, 204.8 MB
__device__ float g_mu[KK * DD];                    // current (unnormalized) mu
__device__ float g_mun[KK * DD];                   // normalized mu
__device__ float g_part[NSPLIT][KK * DD];          // GEMM2 partials, 16.8 MB
__device__ float g_rsum_part[RSPLIT][KK];
__device__ float g_rsum[KK];

// ---------------- row-normalize kernels (D=512, 128 threads, float4) ---------
__device__ __forceinline__ float block_sumsq_512(float4 v) {
    float ss = v.x * v.x + v.y * v.y + v.z * v.z + v.w * v.w;
    #pragma unroll
    for (int off = 16; off > 0; off >>= 1)
        ss += __shfl_xor_sync(0xffffffffu, ss, off);
    __shared__ float wsum[4];
    if ((threadIdx.x & 31) == 0) wsum[threadIdx.x >> 5] = ss;
    __syncthreads();
    return wsum[0] + wsum[1] + wsum[2] + wsum[3];
}

__global__ void norm_data_kernel(const float* __restrict__ in) {
    size_t row = blockIdx.x;
    const float4* ip = (const float4*)(in + row * DD);
    float4 v = ip[threadIdx.x];
    float tot = block_sumsq_512(v);
    float inv = 1.0f / (sqrtf(tot) + 1e-6f);
    float4 o = make_float4(v.x * inv, v.y * inv, v.z * inv, v.w * inv);
    ((float4*)(g_data + row * DD))[threadIdx.x] = o;
}

__global__ void norm_mu_kernel() {
    size_t row = blockIdx.x;
    const float4* ip = (const float4*)(g_mu + row * DD);
    float4 v = ip[threadIdx.x];
    float tot = block_sumsq_512(v);
    float inv = 1.0f / (sqrtf(tot) + 1e-6f);
    float4 o = make_float4(v.x * inv, v.y * inv, v.z * inv, v.w * inv);
    ((float4*)(g_mun + row * DD))[threadIdx.x] = o;
}

__global__ void copy_init_kernel(const float* __restrict__ src) {
    int i = blockIdx.x * blockDim.x + threadIdx.x;
    if (i < KK * DD) g_mu[i] = src[i];
}

// ---------------- GEMM1 + softmax:  r = softmax(T * data @ mu_n^T) -----------
// Block: 64 rows x 256 cols (all K). 256 threads, 8x8 micro-tiles.
// warp w == row-group w: rows w*8..w*8+7, lanes cover all 256 cols (8 each).
__global__ __launch_bounds__(256, 2)
void gemm1_softmax_kernel(const float* __restrict__ tempp, float* __restrict__ rout) {
    __shared__ float As[BK][BM + 4];   // transposed A tile, 16B-aligned rows (68*4=272)
    __shared__ float Bs[BK][KK];       // transposed B tile (mu_n^T)

    const int t = threadIdx.x;
    const int rowbase = blockIdx.x * BM;
    const int rg = t >> 5;             // warp id = row group
    const int cg = t & 31;
    const int row0 = rg * 8;
    const int col0 = cg * 8;

    float acc[8][8] = {};

    const int arow = t >> 2;
    const int ac = (t & 3) * 4;

    for (int k0 = 0; k0 < DD; k0 += BK) {
        // A tile: 64x16, one float4 per thread
        float4 av = make_float4(0.f, 0.f, 0.f, 0.f);
        int gr = rowbase + arow;
        if (gr < NN)
            av = *(const float4*)(g_data + (size_t)gr * DD + k0 + ac);
        As[ac + 0][arow] = av.x;
        As[ac + 1][arow] = av.y;
        As[ac + 2][arow] = av.z;
        As[ac + 3][arow] = av.w;
        // B tile: mu_n rows j=t, 4 float4 each -> Bs[kk][j]
        #pragma unroll
        for (int l = 0; l < 4; l++) {
            float4 bv = *(const float4*)(g_mun + (size_t)t * DD + k0 + l * 4);
            Bs[l * 4 + 0][t] = bv.x;
            Bs[l * 4 + 1][t] = bv.y;
            Bs[l * 4 + 2][t] = bv.z;
            Bs[l * 4 + 3][t] = bv.w;
        }
        __syncthreads();

        #pragma unroll
        for (int kk = 0; kk < BK; kk++) {
            __align__(16) float a[8];
            __align__(16) float b[8];
            *(float4*)&a[0] = *(const float4*)&As[kk][row0];
            *(float4*)&a[4] = *(const float4*)&As[kk][row0 + 4];
            *(float4*)&b[0] = *(const float4*)&Bs[kk][col0];
            *(float4*)&b[4] = *(const float4*)&Bs[kk][col0 + 4];
            #pragma unroll
            for (int i = 0; i < 8; i++)
                #pragma unroll
                for (int j = 0; j < 8; j++)
                    acc[i][j] = fmaf(a[i], b[j], acc[i][j]);
        }
        __syncthreads();
    }

    // softmax epilogue: each warp owns 8 full rows
    const float tv = tempp[0];
    #pragma unroll
    for (int i = 0; i < 8; i++) {
        int grow = rowbase + row0 + i;
        if (grow >= NN) continue;    // uniform within warp
        float m = acc[i][0];
        #pragma unroll
        for (int j = 1; j < 8; j++) m = fmaxf(m, acc[i][j]);
        #pragma unroll
        for (int off = 16; off > 0; off >>= 1)
            m = fmaxf(m, __shfl_xor_sync(0xffffffffu, m, off));
        __align__(16) float e[8];
        float s = 0.f;
        #pragma unroll
        for (int j = 0; j < 8; j++) {
            e[j] = expf(tv * (acc[i][j] - m));
            s += e[j];
        }
        #pragma unroll
        for (int off = 16; off > 0; off >>= 1)
            s += __shfl_xor_sync(0xffffffffu, s, off);
        float inv = 1.0f / s;
        #pragma unroll
        for (int j = 0; j < 8; j++) e[j] *= inv;
        float* rp = rout + (size_t)grow * KK + col0;
        *(float4*)&rp[0] = *(float4*)&e[0];
        *(float4*)&rp[4] = *(float4*)&e[4];
    }
}

// ---------------- rsum: column sums of r (deterministic 2-stage) -------------
__global__ void rsum_part_kernel(const float* __restrict__ r) {
    int sblk = blockIdx.x;
    int col = threadIdx.x;
    int n0 = sblk * RCHUNK;
    int n1 = n0 + RCHUNK; if (n1 > NN) n1 = NN;
    float s0 = 0.f, s1 = 0.f, s2 = 0.f, s3 = 0.f;
    int n = n0;
    for (; n + 4 <= n1; n += 4) {
        s0 += r[(size_t)(n + 0) * KK + col];
        s1 += r[(size_t)(n + 1) * KK + col];
        s2 += r[(size_t)(n + 2) * KK + col];
        s3 += r[(size_t)(n + 3) * KK + col];
    }
    for (; n < n1; n++) s0 += r[(size_t)n * KK + col];
    g_rsum_part[sblk][col] = (s0 + s1) + (s2 + s3);
}

__global__ void rsum_reduce_kernel() {
    int col = threadIdx.x;
    float s = 0.f;
    #pragma unroll 8
    for (int p = 0; p < RSPLIT; p++) s += g_rsum_part[p][col];
    g_rsum[col] = s;
}

// ---------------- GEMM2: mu_part = r^T @ data over an N split ----------------
// Grid (kblk:2, dblk:4, s:32). Block: 128(K) x 128(D) out tile, 256 threads,
// 8x8 micro-tiles, loops its 3125-row N split in 16-row chunks.
__global__ __launch_bounds__(256, 2)
void gemm2_kernel(const float* __restrict__ r) {
    __shared__ float Rs[BN2][KT];
    __shared__ float Ds[BN2][DT];

    const int kblk = blockIdx.x;
    const int dblk = blockIdx.y;
    const int s = blockIdx.z;
    const int t = threadIdx.x;
    const int kg = t >> 4;
    const int dg = t & 15;
    const int row0 = kg * 8;
    const int col0 = dg * 8;

    float acc[8][8] = {};

    const int nbase0 = s * NPS;
    const int nend = nbase0 + NPS;

    for (int nb = nbase0; nb < nend; nb += BN2) {
        #pragma unroll
        for (int l = 0; l < 2; l++) {
            int id = t + l * 256;
            int nr = id >> 5;
            int c = (id & 31) * 4;
            int gn = nb + nr;
            float4 rv = make_float4(0.f, 0.f, 0.f, 0.f);
            float4 dv = make_float4(0.f, 0.f, 0.f, 0.f);
            if (gn < nend) {
                rv = *(const float4*)(r + (size_t)gn * KK + kblk * KT + c);
                dv = *(const float4*)(g_data + (size_t)gn * DD + dblk * DT + c);
            }
            *(float4*)&Rs[nr][c] = rv;
            *(float4*)&Ds[nr][c] = dv;
        }
        __syncthreads();

        #pragma unroll
        for (int nn = 0; nn < BN2; nn++) {
            __align__(16) float a[8];
            __align__(16) float b[8];
            *(float4*)&a[0] = *(const float4*)&Rs[nn][row0];
            *(float4*)&a[4] = *(const float4*)&Rs[nn][row0 + 4];
            *(float4*)&b[0] = *(const float4*)&Ds[nn][col0];
            *(float4*)&b[4] = *(const float4*)&Ds[nn][col0 + 4];
            #pragma unroll
            for (int i = 0; i < 8; i++)
                #pragma unroll
                for (int j = 0; j < 8; j++)
                    acc[i][j] = fmaf(a[i], b[j], acc[i][j]);
        }
        __syncthreads();
    }

    float* p = g_part[s];
    #pragma unroll
    for (int i = 0; i < 8; i++) {
        float* pr = p + (size_t)(kblk * KT + row0 + i) * DD + dblk * DT + col0;
        *(float4*)&pr[0] = *(float4*)&acc[i][0];
        *(float4*)&pr[4] = *(float4*)&acc[i][4];
    }
}

// ---------------- finalize mu: sum partials, divide by rsum ------------------
__global__ void mu_final_kernel(float* __restrict__ extout, int write_ext) {
    int tid = blockIdx.x * blockDim.x + threadIdx.x;
    if (tid >= KK * DD) return;
    int k = tid >> 9;   // /512
    float sum = 0.f;
    #pragma unroll 8
    for (int p = 0; p < NSPLIT; p++) sum += g_part[p][tid];
    float v = sum / g_rsum[k];
    g_mu[tid] = v;
    if (write_ext) extout[tid] = v;
}

// ---------------- launch ------------------------------------------------------
extern "C" void kernel_launch(void* const* d_in, const int* in_sizes, int n_in,
                              void* d_out, int out_size) {
    const float* embeds = (const float*)d_in[0];
    const float* temp   = (const float*)d_in[1];
    const float* init   = (const float*)d_in[2];
    float* out_mu = (float*)d_out;                 // [K*D]
    float* out_r  = (float*)d_out + KK * DD;       // [N*K]; also used as r scratch

    norm_data_kernel<<<NN, 128>>>(embeds);
    copy_init_kernel<<<(KK * DD + 255) / 256, 256>>>(init);

    const int nblk1 = (NN + BM - 1) / BM;          // 1563
    for (int it = 0; it < 11; it++) {
        norm_mu_kernel<<<KK, 128>>>();
        gemm1_softmax_kernel<<<nblk1, 256>>>(temp, out_r);
        rsum_part_kernel<<<RSPLIT, KK>>>(out_r);
        rsum_reduce_kernel<<<1, KK>>>();
        gemm2_kernel<<<dim3(2, 4, NSPLIT), 256>>>(out_r);
        mu_final_kernel<<<(KK * DD + 255) / 256, 256>>>(out_mu, it == 10 ? 1 : 0);
    }
}

// round 10
// speedup vs baseline: 1.9609x; 1.9609x over previous
#include <cuda_runtime.h>
#include <cuda_bf16.h>
#include <math.h>
#include <stdint.h>

// ---------------------------------------------------------------- constants
#define NN 100000
#define DD 512
#define KK 256
#define NPAD 101824            // 37 * 2752; each split = 43 chunks of 64
#define S2 37
#define LSPLIT 2752
#define NCH2 43
#define MT1G 1563              // ceil(NN/64)

// GEMM1 stage: Ah 8K | Al 8K | Bh 32K | Bl 32K = 80K
#define G1_OAL 8192
#define G1_OBH 16384
#define G1_OBL 49152
#define G1_STAGE 81920
#define G1_SMEM (1024 + 2 * G1_STAGE)      // 164864

// GEMM2 stage: Ah 16K | Al 16K | Bh 32K | Bl 32K = 96K
#define G2_OAL 16384
#define G2_OBH 32768
#define G2_OBL 65536
#define G2_STAGE 98304
#define G2_SMEM (2 * G2_STAGE)             // 196608

// ---------------------------------------------------------------- globals
__device__ __nv_bfloat16 g_dhi[(size_t)NN * DD];
__device__ __nv_bfloat16 g_dlo[(size_t)NN * DD];
__device__ __nv_bfloat16 g_dThi[(size_t)DD * NPAD];
__device__ __nv_bfloat16 g_dTlo[(size_t)DD * NPAD];
__device__ __nv_bfloat16 g_rThi[(size_t)KK * NPAD];
__device__ __nv_bfloat16 g_rTlo[(size_t)KK * NPAD];
__device__ __nv_bfloat16 g_muhi[KK * DD];
__device__ __nv_bfloat16 g_mulo[KK * DD];
__device__ float g_mu[KK * DD];
__device__ float g_part[S2][KK * DD];
__device__ float g_rsum[KK];

// ---------------------------------------------------------------- asm helpers
__device__ __forceinline__ uint32_t smem_u32(const void* p) {
    uint32_t a;
    asm("{ .reg .u64 t; cvta.to.shared.u64 t, %1; cvt.u32.u64 %0, t; }" : "=r"(a) : "l"(p));
    return a;
}

__device__ __forceinline__ void cp16(uint32_t dst, const void* src, bool pred) {
    int sz = pred ? 16 : 0;
    asm volatile("cp.async.cg.shared.global [%0], [%1], 16, %2;"
                 :: "r"(dst), "l"(src), "r"(sz) : "memory");
}
#define CP_COMMIT() asm volatile("cp.async.commit_group;" ::: "memory")
#define CP_WAIT1()  asm volatile("cp.async.wait_group 1;" ::: "memory")

__device__ __forceinline__ void ldm4(uint32_t* r, uint32_t addr) {
    asm volatile("ldmatrix.sync.aligned.m8n8.x4.shared.b16 {%0,%1,%2,%3}, [%4];"
                 : "=r"(r[0]), "=r"(r[1]), "=r"(r[2]), "=r"(r[3]) : "r"(addr));
}

__device__ __forceinline__ void mma16816(float* c, const uint32_t* a,
                                         uint32_t b0, uint32_t b1) {
    asm volatile(
        "mma.sync.aligned.m16n8k16.row.col.f32.bf16.bf16.f32 "
        "{%0,%1,%2,%3},{%4,%5,%6,%7},{%8,%9},{%0,%1,%2,%3};"
        : "+f"(c[0]), "+f"(c[1]), "+f"(c[2]), "+f"(c[3])
        : "r"(a[0]), "r"(a[1]), "r"(a[2]), "r"(a[3]), "r"(b0), "r"(b1));
}

// one 64-contraction chunk: warp tile 32(M) x 64(N), 3-product bf16 split
template<int OAL, int OBH, int OBL>
__device__ __forceinline__ void mma_chunk(uint32_t st, float acc[2][8][4],
                                          int lane, int wm, int wn) {
    const int lrow = lane & 15;
    const int lkb = (lane >> 4) * 16;
    #pragma unroll
    for (int ks = 0; ks < 4; ks++) {
        const int kb = ks * 32 + lkb;
        uint32_t ah[2][4], al[2][4];
        #pragma unroll
        for (int i = 0; i < 2; i++) {
            uint32_t bo = (uint32_t)(wm * 32 + i * 16 + lrow) * 128 + kb;
            uint32_t swo = bo ^ ((bo >> 3) & 0x70);
            ldm4(ah[i], st + swo);
            ldm4(al[i], st + OAL + swo);
        }
        #pragma unroll
        for (int j2 = 0; j2 < 4; j2++) {
            uint32_t bo = (uint32_t)(wn * 64 + j2 * 16 + lrow) * 128 + kb;
            uint32_t swo = bo ^ ((bo >> 3) & 0x70);
            uint32_t bh[4], bl[4];
            ldm4(bh, st + OBH + swo);
            ldm4(bl, st + OBL + swo);
            #pragma unroll
            for (int i = 0; i < 2; i++) {
                #pragma unroll
                for (int h = 0; h < 2; h++) {
                    float* c = acc[i][j2 * 2 + h];
                    mma16816(c, ah[i], bh[h], bh[h + 2]);
                    mma16816(c, ah[i], bl[h], bl[h + 2]);
                    mma16816(c, al[i], bh[h], bh[h + 2]);
                }
            }
        }
    }
}

// ---------------------------------------------------------------- small kernels
__device__ __forceinline__ float block_sumsq_512(float4 v) {
    float ss = v.x * v.x + v.y * v.y + v.z * v.z + v.w * v.w;
    #pragma unroll
    for (int off = 16; off > 0; off >>= 1)
        ss += __shfl_xor_sync(0xffffffffu, ss, off);
    __shared__ float wsum[4];
    if ((threadIdx.x & 31) == 0) wsum[threadIdx.x >> 5] = ss;
    __syncthreads();
    return wsum[0] + wsum[1] + wsum[2] + wsum[3];
}

__global__ void k_norm_split(const float* __restrict__ in) {
    size_t row = blockIdx.x;
    float4 v = ((const float4*)(in + row * DD))[threadIdx.x];
    float tot = block_sumsq_512(v);
    float inv = 1.0f / (sqrtf(tot) + 1e-6f);
    float x[4] = {v.x * inv, v.y * inv, v.z * inv, v.w * inv};
    __nv_bfloat16* ph = g_dhi + row * DD + threadIdx.x * 4;
    __nv_bfloat16* pl = g_dlo + row * DD + threadIdx.x * 4;
    #pragma unroll
    for (int i = 0; i < 4; i++) {
        __nv_bfloat16 h = __float2bfloat16(x[i]);
        ph[i] = h;
        pl[i] = __float2bfloat16(x[i] - __bfloat162float(h));
    }
}

__global__ void k_norm_mu_split() {
    size_t row = blockIdx.x;
    float4 v = ((const float4*)(g_mu + row * DD))[threadIdx.x];
    float tot = block_sumsq_512(v);
    float inv = 1.0f / (sqrtf(tot) + 1e-6f);
    float x[4] = {v.x * inv, v.y * inv, v.z * inv, v.w * inv};
    __nv_bfloat16* ph = g_muhi + row * DD + threadIdx.x * 4;
    __nv_bfloat16* pl = g_mulo + row * DD + threadIdx.x * 4;
    #pragma unroll
    for (int i = 0; i < 4; i++) {
        __nv_bfloat16 h = __float2bfloat16(x[i]);
        ph[i] = h;
        pl[i] = __float2bfloat16(x[i] - __bfloat162float(h));
    }
}

__global__ void k_copy_init(const float* __restrict__ src) {
    int i = blockIdx.x * blockDim.x + threadIdx.x;
    if (i < KK * DD) g_mu[i] = src[i];
}

// transpose data hi/lo [n][d] -> dataT hi/lo [d][NPAD] (zero padded)
__global__ void k_transpose() {
    __shared__ __nv_bfloat16 th[32][33];
    __shared__ __nv_bfloat16 tl[32][33];
    int bn = blockIdx.x, bd = blockIdx.y;
    int tx = threadIdx.x, ty = threadIdx.y;
    #pragma unroll
    for (int i = 0; i < 32; i += 8) {
        int n = bn * 32 + ty + i;
        int d = bd * 32 + tx;
        __nv_bfloat16 h = __float2bfloat16(0.f), l = __float2bfloat16(0.f);
        if (n < NN) {
            h = g_dhi[(size_t)n * DD + d];
            l = g_dlo[(size_t)n * DD + d];
        }
        th[ty + i][tx] = h;
        tl[ty + i][tx] = l;
    }
    __syncthreads();
    #pragma unroll
    for (int i = 0; i < 32; i += 8) {
        int d = bd * 32 + ty + i;
        int n = bn * 32 + tx;
        g_dThi[(size_t)d * NPAD + n] = th[tx][ty + i];
        g_dTlo[(size_t)d * NPAD + n] = tl[tx][ty + i];
    }
}

__global__ void k_zero_rpad() {
    int idx = blockIdx.x * blockDim.x + threadIdx.x;
    const int padw = NPAD - NN;
    if (idx < KK * padw) {
        int k = idx / padw;
        int n = NN + (idx - k * padw);
        g_rThi[(size_t)k * NPAD + n] = __float2bfloat16(0.f);
        g_rTlo[(size_t)k * NPAD + n] = __float2bfloat16(0.f);
    }
}

// ---------------------------------------------------------------- GEMM1 + softmax
// block: 64 data rows x 256 clusters; 8 warps (2M x 4N), warp 32x64.
__global__ __launch_bounds__(256, 1)
void k_gemm1(const float* __restrict__ tempp, float* __restrict__ rout, int lastit) {
    extern __shared__ char smem[];
    uint32_t sb = smem_u32(smem);
    const int tid = threadIdx.x;
    const int lane = tid & 31, w = tid >> 5;
    const int wm = w >> 2, wn = w & 3;
    const size_t nbase = (size_t)blockIdx.x * 64;

    float acc[2][8][4] = {};

    auto stage = [&](int c, int buf) {
        uint32_t st = sb + 1024 + buf * G1_STAGE;
        int k0 = c * 64;
        #pragma unroll
        for (int it = 0; it < 2; it++) {
            int idx = tid + it * 256;
            int r = idx >> 3, seg = idx & 7;
            uint32_t bo = (uint32_t)r * 128 + seg * 16;
            uint32_t swo = bo ^ ((bo >> 3) & 0x70);
            size_t gr = nbase + r;
            bool v = gr < NN;
            size_t go = (v ? gr : 0) * DD + k0 + seg * 8;
            cp16(st + swo, g_dhi + go, v);
            cp16(st + G1_OAL + swo, g_dlo + go, v);
        }
        #pragma unroll
        for (int it = 0; it < 8; it++) {
            int idx = tid + it * 256;
            int r = idx >> 3, seg = idx & 7;
            uint32_t bo = (uint32_t)r * 128 + seg * 16;
            uint32_t swo = bo ^ ((bo >> 3) & 0x70);
            size_t go = (size_t)r * DD + k0 + seg * 8;
            cp16(st + G1_OBH + swo, g_muhi + go, true);
            cp16(st + G1_OBL + swo, g_mulo + go, true);
        }
    };

    stage(0, 0); CP_COMMIT();
    stage(1, 1); CP_COMMIT();

    for (int c = 0; c < 8; c++) {
        CP_WAIT1();
        __syncthreads();
        mma_chunk<G1_OAL, G1_OBH, G1_OBL>(sb + 1024 + (c & 1) * G1_STAGE, acc, lane, wm, wn);
        __syncthreads();
        if (c + 2 < 8) stage(c + 2, c & 1);
        CP_COMMIT();
    }

    // ---------------- softmax epilogue ----------------
    const float tv = tempp[0];
    const int g = lane >> 2, q = lane & 3;
    float* sums = (float*)smem;   // [64][4]

    // exp in place
    #pragma unroll
    for (int i = 0; i < 2; i++)
        #pragma unroll
        for (int jn = 0; jn < 8; jn++)
            #pragma unroll
            for (int r = 0; r < 4; r++)
                acc[i][jn][r] = __expf(tv * acc[i][jn][r]);

    // per-row partial sums (quad reduce), write [row][wn]
    #pragma unroll
    for (int i = 0; i < 2; i++) {
        #pragma unroll
        for (int h = 0; h < 2; h++) {
            float p = 0.f;
            #pragma unroll
            for (int jn = 0; jn < 8; jn++)
                p += acc[i][jn][h * 2] + acc[i][jn][h * 2 + 1];
            p += __shfl_xor_sync(0xffffffffu, p, 1);
            p += __shfl_xor_sync(0xffffffffu, p, 2);
            if (q == 0) {
                int rr = wm * 32 + i * 16 + h * 8 + g;
                sums[rr * 4 + wn] = p;
            }
        }
    }
    __syncthreads();

    // write rT hi/lo into swizzled SMEM [col][row], plus fp32 rout on last iter
    #pragma unroll
    for (int i = 0; i < 2; i++) {
        #pragma unroll
        for (int h = 0; h < 2; h++) {
            int rr = wm * 32 + i * 16 + h * 8 + g;
            size_t gr = nbase + rr;
            bool v = gr < NN;
            float inv = 1.0f / (sums[rr * 4 + 0] + sums[rr * 4 + 1] +
                                sums[rr * 4 + 2] + sums[rr * 4 + 3]);
            #pragma unroll
            for (int jn = 0; jn < 8; jn++) {
                #pragma unroll
                for (int cc = 0; cc < 2; cc++) {
                    float e = v ? acc[i][jn][h * 2 + cc] * inv : 0.f;
                    int col = wn * 64 + jn * 8 + q * 2 + cc;
                    __nv_bfloat16 hi = __float2bfloat16(e);
                    __nv_bfloat16 lo = __float2bfloat16(e - __bfloat162float(hi));
                    int widx = col * 32 + (((rr >> 1)) ^ ((col & 7) << 2));
                    int boff = widx * 4 + (rr & 1) * 2;
                    *(__nv_bfloat16*)(smem + 1024 + boff) = hi;
                    *(__nv_bfloat16*)(smem + 1024 + 32768 + boff) = lo;
                    if (lastit && v) rout[gr * (size_t)KK + col] = e;
                }
            }
        }
    }
    __syncthreads();

    // coalesced transposed store: thread -> (col, 16-row part)
    const int part = tid & 3, colb = tid >> 2;
    #pragma unroll
    for (int cc = 0; cc < 4; cc++) {
        int col = colb + cc * 64;
        int xorv = (col & 7) << 2;
        uint32_t wA = (uint32_t)(col * 32 + ((part * 8) ^ xorv));
        uint32_t wB = wA ^ 4;
        uint4 vh0 = *(const uint4*)(smem + 1024 + wA * 4);
        uint4 vh1 = *(const uint4*)(smem + 1024 + wB * 4);
        uint4 vl0 = *(const uint4*)(smem + 1024 + 32768 + wA * 4);
        uint4 vl1 = *(const uint4*)(smem + 1024 + 32768 + wB * 4);
        size_t dsto = (size_t)col * NPAD + nbase + part * 16;
        *(uint4*)(g_rThi + dsto) = vh0;
        *(uint4*)(g_rThi + dsto + 8) = vh1;
        *(uint4*)(g_rTlo + dsto) = vl0;
        *(uint4*)(g_rTlo + dsto + 8) = vl1;
    }
}

// ---------------------------------------------------------------- rsum
__global__ void k_rsum() {
    int k = blockIdx.x;
    int tid = threadIdx.x;
    const uint4* ph = (const uint4*)(g_rThi + (size_t)k * NPAD);
    const uint4* pl = (const uint4*)(g_rTlo + (size_t)k * NPAD);
    const int nv = NPAD / 8;
    float s = 0.f;
    for (int i = tid; i < nv; i += 256) {
        uint4 a = ph[i], b = pl[i];
        uint32_t u[8] = {a.x, a.y, a.z, a.w, b.x, b.y, b.z, b.w};
        #pragma unroll
        for (int qd = 0; qd < 8; qd++) {
            __nv_bfloat162 h2 = *reinterpret_cast<__nv_bfloat162*>(&u[qd]);
            float2 f = __bfloat1622float2(h2);
            s += f.x + f.y;
        }
    }
    #pragma unroll
    for (int off = 16; off > 0; off >>= 1)
        s += __shfl_xor_sync(0xffffffffu, s, off);
    __shared__ float ws[8];
    if ((tid & 31) == 0) ws[tid >> 5] = s;
    __syncthreads();
    if (tid == 0) {
        float t = 0.f;
        #pragma unroll
        for (int i = 0; i < 8; i++) t += ws[i];
        g_rsum[k] = t;
    }
}

// ---------------------------------------------------------------- GEMM2
// block: 128 clusters x 256 d-cols; 16 warps (4M x 4N), warp 32x64.
__global__ __launch_bounds__(512, 1)
void k_gemm2() {
    extern __shared__ char smem[];
    uint32_t sb = smem_u32(smem);
    const int tid = threadIdx.x;
    const int lane = tid & 31, w = tid >> 5;
    const int wm = w >> 2, wn = w & 3;
    const int mt = blockIdx.x, nt = blockIdx.y, sp = blockIdx.z;
    const size_t nb0 = (size_t)sp * LSPLIT;

    float acc[2][8][4] = {};

    auto stage = [&](int c, int buf) {
        uint32_t st = sb + buf * G2_STAGE;
        size_t n0 = nb0 + (size_t)c * 64;
        #pragma unroll
        for (int it = 0; it < 2; it++) {
            int idx = tid + it * 512;
            int r = idx >> 3, seg = idx & 7;
            uint32_t bo = (uint32_t)r * 128 + seg * 16;
            uint32_t swo = bo ^ ((bo >> 3) & 0x70);
            size_t go = (size_t)(mt * 128 + r) * NPAD + n0 + seg * 8;
            cp16(st + swo, g_rThi + go, true);
            cp16(st + G2_OAL + swo, g_rTlo + go, true);
        }
        #pragma unroll
        for (int it = 0; it < 4; it++) {
            int idx = tid + it * 512;
            int r = idx >> 3, seg = idx & 7;
            uint32_t bo = (uint32_t)r * 128 + seg * 16;
            uint32_t swo = bo ^ ((bo >> 3) & 0x70);
            size_t go = (size_t)(nt * 256 + r) * NPAD + n0 + seg * 8;
            cp16(st + G2_OBH + swo, g_dThi + go, true);
            cp16(st + G2_OBL + swo, g_dTlo + go, true);
        }
    };

    stage(0, 0); CP_COMMIT();
    stage(1, 1); CP_COMMIT();

    for (int c = 0; c < NCH2; c++) {
        CP_WAIT1();
        __syncthreads();
        mma_chunk<G2_OAL, G2_OBH, G2_OBL>(sb + (c & 1) * G2_STAGE, acc, lane, wm, wn);
        __syncthreads();
        if (c + 2 < NCH2) stage(c + 2, c & 1);
        CP_COMMIT();
    }

    // epilogue: write 128x256 fp32 partial
    const int g = lane >> 2, q = lane & 3;
    float* p = g_part[sp];
    #pragma unroll
    for (int i = 0; i < 2; i++) {
        #pragma unroll
        for (int h = 0; h < 2; h++) {
            int rr = wm * 32 + i * 16 + h * 8 + g;
            float* dst = p + (size_t)(mt * 128 + rr) * DD + nt * 256 + wn * 64;
            #pragma unroll
            for (int jn = 0; jn < 8; jn++) {
                float2 v = make_float2(acc[i][jn][h * 2], acc[i][jn][h * 2 + 1]);
                *(float2*)(dst + jn * 8 + q * 2) = v;
            }
        }
    }
}

// ---------------------------------------------------------------- finalize mu
__global__ void k_mu_final(float* __restrict__ extout, int write_ext) {
    int tid = blockIdx.x * blockDim.x + threadIdx.x;
    if (tid >= KK * DD) return;
    int k = tid >> 9;
    float s = 0.f;
    #pragma unroll
    for (int p = 0; p < S2; p++) s += g_part[p][tid];
    float v = s / g_rsum[k];
    g_mu[tid] = v;
    if (write_ext) extout[tid] = v;
}

// ---------------------------------------------------------------- launch
extern "C" void kernel_launch(void* const* d_in, const int* in_sizes, int n_in,
                              void* d_out, int out_size) {
    const float* embeds = (const float*)d_in[0];
    const float* temp   = (const float*)d_in[1];
    const float* init   = (const float*)d_in[2];
    float* out_mu = (float*)d_out;
    float* out_r  = (float*)d_out + KK * DD;

    cudaFuncSetAttribute(k_gemm1, cudaFuncAttributeMaxDynamicSharedMemorySize, G1_SMEM);
    cudaFuncSetAttribute(k_gemm2, cudaFuncAttributeMaxDynamicSharedMemorySize, G2_SMEM);

    k_norm_split<<<NN, 128>>>(embeds);
    k_transpose<<<dim3(NPAD / 32, DD / 32), dim3(32, 8)>>>();
    k_zero_rpad<<<(KK * (NPAD - NN) + 1023) / 1024, 1024>>>();
    k_copy_init<<<(KK * DD + 255) / 256, 256>>>(init);

    for (int it = 0; it < 11; it++) {
        k_norm_mu_split<<<KK, 128>>>();
        k_gemm1<<<MT1G, 256, G1_SMEM>>>(temp, out_r, it == 10 ? 1 : 0);
        k_rsum<<<KK, 256>>>();
        k_gemm2<<<dim3(2, 2, S2), 512, G2_SMEM>>>();
        k_mu_final<<<(KK * DD + 255) / 256, 256>>>(out_mu, it == 10 ? 1 : 0);
    }
}

// round 12
// speedup vs baseline: 3.0219x; 1.5410x over previous
#include <cuda_runtime.h>
#include <cuda_bf16.h>
#include <math.h>
#include <stdint.h>

// ---------------------------------------------------------------- constants
#define NN 100000
#define DD 512
#define KK 256
#define RB1 782                 // ceil(NN/128) row-blocks
#define NROWPAD (RB1 * 128)     // 100096
#define NCT 1591                // n-chunks of 64: NPAD = 101824 = 37*43*64
#define NPAD (NCT * 64)
#define S2 37
#define NC2 43                  // chunks per GEMM2 split

// stage layout (bytes, within one buffer): Ah 16K | Al 16K | Bh 32K | Bl 32K
#define OFF_AL 16384
#define OFF_BH 32768
#define OFF_BL 65536
#define STAGE 98304
#define STAGE_TX 98304
#define OFF_BUF 4096
#define SMEM_TOT (OFF_BUF + 2 * STAGE)    // 200704

// ---------------------------------------------------------------- globals
__device__ __nv_bfloat16 g_dhi[(size_t)RB1 * 8 * 8192];    // tiled 128x64 sw
__device__ __nv_bfloat16 g_dlo[(size_t)RB1 * 8 * 8192];
__device__ __nv_bfloat16 g_dThi[(size_t)2 * NCT * 16384];  // tiled 256x64 sw
__device__ __nv_bfloat16 g_dTlo[(size_t)2 * NCT * 16384];
__device__ __nv_bfloat16 g_rThi[(size_t)2 * NCT * 8192];   // tiled 128x64 sw
__device__ __nv_bfloat16 g_rTlo[(size_t)2 * NCT * 8192];
__device__ __nv_bfloat16 g_muhi[8 * 16384];                // tiled 256x64 sw
__device__ __nv_bfloat16 g_mulo[8 * 16384];
__device__ float g_mu[KK * DD];
__device__ float g_part[S2][KK * DD];
__device__ float g_rsum[KK];

// ---------------------------------------------------------------- asm helpers
__device__ __forceinline__ uint32_t smem_u32(const void* p) {
    uint32_t a;
    asm("{ .reg .u64 t; cvta.to.shared.u64 t, %1; cvt.u32.u64 %0, t; }" : "=r"(a) : "l"(p));
    return a;
}
__device__ __forceinline__ uint32_t swz(uint32_t bo) { return bo ^ ((bo >> 3) & 0x70); }

__device__ __forceinline__ void bulk_ld(uint32_t dst, const void* src, int bytes, uint32_t mb) {
    asm volatile(
        "cp.async.bulk.shared::cta.global.mbarrier::complete_tx::bytes [%0], [%1], %2, [%3];"
        :: "r"(dst), "l"(src), "r"(bytes), "r"(mb) : "memory");
}
__device__ __forceinline__ void bulk_st(void* dst, uint32_t src, int bytes) {
    asm volatile("cp.async.bulk.global.shared::cta.bulk_group [%0], [%1], %2;"
                 :: "l"(dst), "r"(src), "r"(bytes) : "memory");
}
#define BULK_COMMIT() asm volatile("cp.async.bulk.commit_group;" ::: "memory")
#define BULK_WAIT0()  asm volatile("cp.async.bulk.wait_group 0;" ::: "memory")
#define MB_INIT(mb, n) asm volatile("mbarrier.init.shared.b64 [%0], %1;" :: "r"((uint32_t)(mb)), "r"((uint32_t)(n)) : "memory")
#define MB_EXPECT(mb, tx) asm volatile("mbarrier.arrive.expect_tx.shared.b64 _, [%0], %1;" :: "r"((uint32_t)(mb)), "r"((uint32_t)(tx)) : "memory")
#define FENCE_ASYNC() asm volatile("fence.proxy.async.shared::cta;" ::: "memory")

__device__ __forceinline__ void mbar_wait(uint32_t mb, int par) {
    asm volatile(
        "{\n\t.reg .pred P;\n\t"
        "WL_%=:\n\t"
        "mbarrier.try_wait.parity.acquire.cta.shared::cta.b64 P, [%0], %1, 0x989680;\n\t"
        "@P bra.uni WD_%=;\n\t"
        "bra.uni WL_%=;\n\t"
        "WD_%=:\n\t}"
        :: "r"(mb), "r"((uint32_t)par) : "memory");
}

__device__ __forceinline__ void ldm4(uint32_t* r, uint32_t addr) {
    asm volatile("ldmatrix.sync.aligned.m8n8.x4.shared.b16 {%0,%1,%2,%3}, [%4];"
                 : "=r"(r[0]), "=r"(r[1]), "=r"(r[2]), "=r"(r[3]) : "r"(addr));
}
__device__ __forceinline__ void mma16816(float* c, const uint32_t* a,
                                         uint32_t b0, uint32_t b1) {
    asm volatile(
        "mma.sync.aligned.m16n8k16.row.col.f32.bf16.bf16.f32 "
        "{%0,%1,%2,%3},{%4,%5,%6,%7},{%8,%9},{%0,%1,%2,%3};"
        : "+f"(c[0]), "+f"(c[1]), "+f"(c[2]), "+f"(c[3])
        : "r"(a[0]), "r"(a[1]), "r"(a[2]), "r"(a[3]), "r"(b0), "r"(b1));
}

// warp tile 64(M) x 64(N) over one 64-contraction chunk; 3-product bf16 split.
__device__ __forceinline__ void mma_chunk(uint32_t st, float acc[4][8][4],
                                          int lane, int wm, int wn) {
    const int lrow = lane & 15;
    const int lkb = (lane >> 4) * 16;
    #pragma unroll
    for (int ks = 0; ks < 4; ks++) {
        const int kb = ks * 32 + lkb;
        uint32_t ah[4][4], al[4][4];
        #pragma unroll
        for (int i = 0; i < 4; i++) {
            uint32_t swo = swz((uint32_t)(wm * 64 + i * 16 + lrow) * 128 + kb);
            ldm4(ah[i], st + swo);
            ldm4(al[i], st + OFF_AL + swo);
        }
        #pragma unroll
        for (int j2 = 0; j2 < 4; j2++) {
            uint32_t swo = swz((uint32_t)(wn * 64 + j2 * 16 + lrow) * 128 + kb);
            uint32_t bh[4], bl[4];
            ldm4(bh, st + OFF_BH + swo);
            ldm4(bl, st + OFF_BL + swo);
            #pragma unroll
            for (int i = 0; i < 4; i++) {
                #pragma unroll
                for (int h = 0; h < 2; h++) {
                    float* c = acc[i][j2 * 2 + h];
                    mma16816(c, ah[i], bh[h], bh[h + 2]);
                    mma16816(c, ah[i], bl[h], bl[h + 2]);
                    mma16816(c, al[i], bh[h], bh[h + 2]);
                }
            }
        }
    }
}

// ---------------------------------------------------------------- small kernels
__device__ __forceinline__ float block_sumsq_512(float4 v) {
    float ss = v.x * v.x + v.y * v.y + v.z * v.z + v.w * v.w;
    #pragma unroll
    for (int off = 16; off > 0; off >>= 1)
        ss += __shfl_xor_sync(0xffffffffu, ss, off);
    __shared__ float wsum[4];
    if ((threadIdx.x & 31) == 0) wsum[threadIdx.x >> 5] = ss;
    __syncthreads();
    return wsum[0] + wsum[1] + wsum[2] + wsum[3];
}

__device__ __forceinline__ void split_store(char* basehi, char* baselo,
                                            size_t byteoff, const float* x) {
    __nv_bfloat16 h[4], l[4];
    #pragma unroll
    for (int i = 0; i < 4; i++) {
        h[i] = __float2bfloat16(x[i]);
        l[i] = __float2bfloat16(x[i] - __bfloat162float(h[i]));
    }
    *(uint2*)(basehi + byteoff) = *(const uint2*)h;
    *(uint2*)(baselo + byteoff) = *(const uint2*)l;
}

__global__ void k_zero_dtail() {
    int i = blockIdx.x * 256 + threadIdx.x;
    if (i < 65536) {
        size_t base = (size_t)781 * 8 * 8192 + i;
        g_dhi[base] = __float2bfloat16(0.f);
        g_dlo[base] = __float2bfloat16(0.f);
    }
}

__global__ void k_zero_rT() {
    int i = blockIdx.x * 256 + threadIdx.x;
    const int per_mt = 27 * 8192;
    if (i < 2 * per_mt) {
        int mt = i / per_mt, rem = i - mt * per_mt;
        int nc = 1564 + rem / 8192, off = rem & 8191;
        size_t e = ((size_t)mt * NCT + nc) * 8192 + off;
        g_rThi[e] = __float2bfloat16(0.f);
        g_rTlo[e] = __float2bfloat16(0.f);
    }
}

// normalize data row -> tiled swizzled hi/lo
__global__ void k_norm_split(const float* __restrict__ in) {
    size_t row = blockIdx.x;
    float4 v = ((const float4*)(in + row * DD))[threadIdx.x];
    float tot = block_sumsq_512(v);
    float inv = 1.0f / (sqrtf(tot) + 1e-6f);
    float x[4] = {v.x * inv, v.y * inv, v.z * inv, v.w * inv};
    int d = threadIdx.x * 4;
    int rb = (int)(row >> 7), rr = (int)(row & 127), kc = d >> 6;
    size_t bo = (size_t)(rb * 8 + kc) * 16384 + swz((uint32_t)rr * 128 + (d & 63) * 2);
    split_store((char*)g_dhi, (char*)g_dlo, bo, x);
}

// normalize mu row -> tiled swizzled hi/lo (B tiles: 256x64)
__global__ void k_norm_mu() {
    size_t row = blockIdx.x;
    float4 v = ((const float4*)(g_mu + row * DD))[threadIdx.x];
    float tot = block_sumsq_512(v);
    float inv = 1.0f / (sqrtf(tot) + 1e-6f);
    float x[4] = {v.x * inv, v.y * inv, v.z * inv, v.w * inv};
    int d = threadIdx.x * 4;
    int kc = d >> 6;
    size_t bo = (size_t)kc * 32768 + swz((uint32_t)row * 128 + (d & 63) * 2);
    split_store((char*)g_muhi, (char*)g_mulo, bo, x);
}

__global__ void k_copy_init(const float* __restrict__ src) {
    int i = blockIdx.x * blockDim.x + threadIdx.x;
    if (i < KK * DD) g_mu[i] = src[i];
}

// build dataT tiles (256 d-rows x 64 n-cols, swizzled) from data tiles
__global__ void k_transpose() {
    __shared__ __nv_bfloat16 th[64][65];
    __shared__ __nv_bfloat16 tl[64][65];
    int nc = blockIdx.x, nt = blockIdx.y;
    int tid = threadIdx.x;
    int rb = nc >> 1, nb = (nc & 1) * 64;
    for (int sub = 0; sub < 4; sub++) {
        int kc = nt * 4 + sub;
        // read 64 n-rows x 64 d-cols from data tile (rb, kc)
        #pragma unroll
        for (int e = 0; e < 16; e++) {
            int id = tid + e * 256;
            int rn = id >> 6, dc = id & 63;
            __nv_bfloat16 h = __float2bfloat16(0.f), l = __float2bfloat16(0.f);
            if (nc < 1564) {
                size_t bo = (size_t)(rb * 8 + kc) * 16384 +
                            swz((uint32_t)(nb + rn) * 128 + dc * 2);
                h = *(const __nv_bfloat16*)((const char*)g_dhi + bo);
                l = *(const __nv_bfloat16*)((const char*)g_dlo + bo);
            }
            th[rn][dc] = h;
            tl[rn][dc] = l;
        }
        __syncthreads();
        // write transposed: rows = d, cols = n, into dataT tile (nt, nc)
        #pragma unroll
        for (int e = 0; e < 16; e++) {
            int id = tid + e * 256;
            int dr = id >> 6, nn = id & 63;
            size_t bo = ((size_t)nt * NCT + nc) * 32768 +
                        swz((uint32_t)(sub * 64 + dr) * 128 + nn * 2);
            *(__nv_bfloat16*)((char*)g_dThi + bo) = th[nn][dr];
            *(__nv_bfloat16*)((char*)g_dTlo + bo) = tl[nn][dr];
        }
        __syncthreads();
    }
}

// ---------------------------------------------------------------- GEMM1 + softmax
// block: 128 data rows x 256 clusters; 8 warps (2M x 4N), warp 64x64.
__global__ __launch_bounds__(256, 1)
void k_gemm1(const float* __restrict__ tempp, float* __restrict__ rout, int lastit) {
    extern __shared__ char smem[];
    uint32_t sb = smem_u32(smem);
    const int tid = threadIdx.x;
    const int lane = tid & 31, w = tid >> 5;
    const int wm = w >> 2, wn = w & 3;
    const int rb = blockIdx.x;
    const size_t nbase = (size_t)rb * 128;
    const uint32_t mb0 = sb + 8, mb1 = sb + 16;

    float acc[4][8][4] = {};

    auto issue = [&](int c, int buf, uint32_t mb) {
        uint32_t st = sb + OFF_BUF + buf * STAGE;
        MB_EXPECT(mb, STAGE_TX);
        bulk_ld(st,          (const char*)g_dhi + (size_t)(rb * 8 + c) * 16384, 16384, mb);
        bulk_ld(st + OFF_AL, (const char*)g_dlo + (size_t)(rb * 8 + c) * 16384, 16384, mb);
        bulk_ld(st + OFF_BH, (const char*)g_muhi + (size_t)c * 32768, 32768, mb);
        bulk_ld(st + OFF_BL, (const char*)g_mulo + (size_t)c * 32768, 32768, mb);
    };

    if (tid == 0) {
        MB_INIT(mb0, 1);
        MB_INIT(mb1, 1);
        FENCE_ASYNC();
        issue(0, 0, mb0);
        issue(1, 1, mb1);
    }
    __syncthreads();

    int ph0 = 0, ph1 = 0;
    for (int c = 0; c < 8; c++) {
        int buf = c & 1;
        uint32_t mb = buf ? mb1 : mb0;
        if (buf == 0) { mbar_wait(mb0, ph0); ph0 ^= 1; }
        else          { mbar_wait(mb1, ph1); ph1 ^= 1; }
        mma_chunk(sb + OFF_BUF + buf * STAGE, acc, lane, wm, wn);
        __syncthreads();
        if (c + 2 < 8 && tid == 0) { FENCE_ASYNC(); issue(c + 2, buf, mb); }
    }

    // ---------------- softmax epilogue ----------------
    const float tv = tempp[0];
    const int g = lane >> 2, q = lane & 3;
    float* sums = (float*)(smem + 64);   // [128][4]

    #pragma unroll
    for (int i = 0; i < 4; i++)
        #pragma unroll
        for (int jn = 0; jn < 8; jn++)
            #pragma unroll
            for (int r = 0; r < 4; r++)
                acc[i][jn][r] = __expf(tv * acc[i][jn][r]);

    #pragma unroll
    for (int i = 0; i < 4; i++) {
        #pragma unroll
        for (int h = 0; h < 2; h++) {
            float p = 0.f;
            #pragma unroll
            for (int jn = 0; jn < 8; jn++)
                p += acc[i][jn][h * 2] + acc[i][jn][h * 2 + 1];
            p += __shfl_xor_sync(0xffffffffu, p, 1);
            p += __shfl_xor_sync(0xffffffffu, p, 2);
            if (q == 0) {
                int rr = wm * 64 + i * 16 + h * 8 + g;
                sums[rr * 4 + wn] = p;
            }
        }
    }
    __syncthreads();

    // write rT tiles into SMEM (4 tiles hi @ +0..64K, 4 tiles lo @ +64K..128K)
    char* tb = smem + OFF_BUF;
    #pragma unroll
    for (int i = 0; i < 4; i++) {
        #pragma unroll
        for (int h = 0; h < 2; h++) {
            int rr = wm * 64 + i * 16 + h * 8 + g;
            size_t gr = nbase + rr;
            bool v = gr < NN;
            float inv = 1.0f / (sums[rr * 4 + 0] + sums[rr * 4 + 1] +
                                sums[rr * 4 + 2] + sums[rr * 4 + 3]);
            int ncl = rr >> 6, nn = rr & 63;
            #pragma unroll
            for (int jn = 0; jn < 8; jn++) {
                #pragma unroll
                for (int cc = 0; cc < 2; cc++) {
                    float e = v ? acc[i][jn][h * 2 + cc] * inv : 0.f;
                    int k = wn * 64 + jn * 8 + q * 2 + cc;
                    int mt = k >> 7, kr = k & 127;
                    uint32_t bo = (mt * 2 + ncl) * 16384 + swz((uint32_t)kr * 128 + nn * 2);
                    __nv_bfloat16 hi = __float2bfloat16(e);
                    *(__nv_bfloat16*)(tb + bo) = hi;
                    *(__nv_bfloat16*)(tb + 65536 + bo) =
                        __float2bfloat16(e - __bfloat162float(hi));
                    if (lastit && v) rout[gr * (size_t)KK + k] = e;
                }
            }
        }
    }
    __syncthreads();
    FENCE_ASYNC();
    if (tid < 8) {
        int arr = tid & 1, t = tid >> 1;
        int mt = t >> 1, ncl = t & 1;
        size_t dsto = ((size_t)mt * NCT + (rb * 2 + ncl)) * 16384;
        char* dst = (arr ? (char*)g_rTlo : (char*)g_rThi) + dsto;
        bulk_st(dst, sb + OFF_BUF + t * 16384 + arr * 65536, 16384);
        BULK_COMMIT();
        BULK_WAIT0();
    }
}

// ---------------------------------------------------------------- rsum
__global__ void k_rsum() {
    int k = blockIdx.x;
    int tid = threadIdx.x;
    int mt = k >> 7, r = k & 127;
    float s = 0.f;
    for (int nc = tid; nc < NCT; nc += 256) {
        const char* bh = (const char*)g_rThi + ((size_t)mt * NCT + nc) * 16384 + r * 128;
        const char* bl = (const char*)g_rTlo + ((size_t)mt * NCT + nc) * 16384 + r * 128;
        #pragma unroll
        for (int u = 0; u < 8; u++) {
            uint4 a = *(const uint4*)(bh + u * 16);
            uint4 b = *(const uint4*)(bl + u * 16);
            uint32_t uu[8] = {a.x, a.y, a.z, a.w, b.x, b.y, b.z, b.w};
            #pragma unroll
            for (int qd = 0; qd < 8; qd++) {
                __nv_bfloat162 h2 = *reinterpret_cast<__nv_bfloat162*>(&uu[qd]);
                float2 f = __bfloat1622float2(h2);
                s += f.x + f.y;
            }
        }
    }
    #pragma unroll
    for (int off = 16; off > 0; off >>= 1)
        s += __shfl_xor_sync(0xffffffffu, s, off);
    __shared__ float ws[8];
    if ((tid & 31) == 0) ws[tid >> 5] = s;
    __syncthreads();
    if (tid == 0) {
        float t = 0.f;
        #pragma unroll
        for (int i = 0; i < 8; i++) t += ws[i];
        g_rsum[k] = t;
    }
}

// ---------------------------------------------------------------- GEMM2
// block: 128 clusters x 256 d-cols; 8 warps (2M x 4N), warp 64x64.
__global__ __launch_bounds__(256, 1)
void k_gemm2() {
    extern __shared__ char smem[];
    uint32_t sb = smem_u32(smem);
    const int tid = threadIdx.x;
    const int lane = tid & 31, w = tid >> 5;
    const int wm = w >> 2, wn = w & 3;
    const int mt = blockIdx.x, nt = blockIdx.y, sp = blockIdx.z;
    const uint32_t mb0 = sb + 8, mb1 = sb + 16;

    float acc[4][8][4] = {};

    auto issue = [&](int c, int buf, uint32_t mb) {
        uint32_t st = sb + OFF_BUF + buf * STAGE;
        size_t nc = (size_t)sp * NC2 + c;
        MB_EXPECT(mb, STAGE_TX);
        bulk_ld(st,          (const char*)g_rThi + ((size_t)mt * NCT + nc) * 16384, 16384, mb);
        bulk_ld(st + OFF_AL, (const char*)g_rTlo + ((size_t)mt * NCT + nc) * 16384, 16384, mb);
        bulk_ld(st + OFF_BH, (const char*)g_dThi + ((size_t)nt * NCT + nc) * 32768, 32768, mb);
        bulk_ld(st + OFF_BL, (const char*)g_dTlo + ((size_t)nt * NCT + nc) * 32768, 32768, mb);
    };

    if (tid == 0) {
        MB_INIT(mb0, 1);
        MB_INIT(mb1, 1);
        FENCE_ASYNC();
        issue(0, 0, mb0);
        issue(1, 1, mb1);
    }
    __syncthreads();

    int ph0 = 0, ph1 = 0;
    for (int c = 0; c < NC2; c++) {
        int buf = c & 1;
        uint32_t mb = buf ? mb1 : mb0;
        if (buf == 0) { mbar_wait(mb0, ph0); ph0 ^= 1; }
        else          { mbar_wait(mb1, ph1); ph1 ^= 1; }
        mma_chunk(sb + OFF_BUF + buf * STAGE, acc, lane, wm, wn);
        __syncthreads();
        if (c + 2 < NC2 && tid == 0) { FENCE_ASYNC(); issue(c + 2, buf, mb); }
    }

    // epilogue: 128x256 fp32 partial
    const int g = lane >> 2, q = lane & 3;
    float* p = g_part[sp];
    #pragma unroll
    for (int i = 0; i < 4; i++) {
        #pragma unroll
        for (int h = 0; h < 2; h++) {
            int rr = wm * 64 + i * 16 + h * 8 + g;
            float* dst = p + (size_t)(mt * 128 + rr) * DD + nt * 256 + wn * 64;
            #pragma unroll
            for (int jn = 0; jn < 8; jn++) {
                float2 v = make_float2(acc[i][jn][h * 2], acc[i][jn][h * 2 + 1]);
                *(float2*)(dst + jn * 8 + q * 2) = v;
            }
        }
    }
}

// ---------------------------------------------------------------- finalize mu
__global__ void k_mu_final(float* __restrict__ extout, int write_ext) {
    int tid = blockIdx.x * blockDim.x + threadIdx.x;
    if (tid >= KK * DD) return;
    int k = tid >> 9;
    float s = 0.f;
    #pragma unroll
    for (int p = 0; p < S2; p++) s += g_part[p][tid];
    float v = s / g_rsum[k];
    g_mu[tid] = v;
    if (write_ext) extout[tid] = v;
}

// ---------------------------------------------------------------- launch
extern "C" void kernel_launch(void* const* d_in, const int* in_sizes, int n_in,
                              void* d_out, int out_size) {
    const float* embeds = (const float*)d_in[0];
    const float* temp   = (const float*)d_in[1];
    const float* init   = (const float*)d_in[2];
    float* out_mu = (float*)d_out;
    float* out_r  = (float*)d_out + KK * DD;

    cudaFuncSetAttribute(k_gemm1, cudaFuncAttributeMaxDynamicSharedMemorySize, SMEM_TOT);
    cudaFuncSetAttribute(k_gemm2, cudaFuncAttributeMaxDynamicSharedMemorySize, SMEM_TOT);

    k_zero_dtail<<<256, 256>>>();
    k_zero_rT<<<1728, 256>>>();
    k_norm_split<<<NN, 128>>>(embeds);
    k_transpose<<<dim3(NCT, 2), 256>>>();
    k_copy_init<<<(KK * DD + 255) / 256, 256>>>(init);

    for (int it = 0; it < 11; it++) {
        k_norm_mu<<<KK, 128>>>();
        k_gemm1<<<RB1, 256, SMEM_TOT>>>(temp, out_r, it == 10 ? 1 : 0);
        k_rsum<<<KK, 256>>>();
        k_gemm2<<<dim3(2, 2, S2), 256, SMEM_TOT>>>();
        k_mu_final<<<(KK * DD + 255) / 256, 256>>>(out_mu, it == 10 ? 1 : 0);
    }
}